// round 16
// baseline (speedup 1.0000x reference)
#include <cuda_runtime.h>
#include <cuda_bf16.h>
#include <cstdint>
#include <math.h>

// Problem constants
#define NB 32
#define NS 1024
#define NC 12
#define NE 256
#define NH 512
#define NT 50
#define NBS (NB*NS)      // 32768 words

// ---------------- device scratch (no cudaMalloc allowed) ----------------
__device__ float g_cproj[128 * 4 * NE];              // [128][1024] char input proj (+bc)
__device__ float g_cc[NBS * NE];                     // char LSTM c
__device__ float g_gates[NBS * 4 * NE];              // char gates scratch
__device__ __nv_bfloat16 g_h3[NBS * 3 * NE];         // h triple bf16 [hi,lo,hi]
__device__ __nv_bfloat16 g_wchh3[4 * NE * 3 * NE];   // Wc_hh triple [hi,hi,lo]
__device__ __nv_bfloat16 g_xw3[NBS * 3 * 2 * NE];    // [we;char_feat] triple [hi,lo,hi]
__device__ __nv_bfloat16 g_wwih3[4 * NH * 3 * 2 * NE]; // Ww_ih triple [hi,hi,lo]
__device__ float g_gin[NBS * 4 * NH];                // word input projection
__device__ float g_whs[NS * NB * NH];                // word hidden trace [t][b][h]
__device__ int g_done[128];                          // per-block step flags

__device__ __forceinline__ float sigm(float x) { return 1.0f / (1.0f + expf(-x)); }

// B-side triple conversion body: [hi, hi, lo] per element, 8 elems per idx
__device__ __forceinline__ void conv3_body(const float* __restrict__ src,
                                           __nv_bfloat16* __restrict__ dst, int idx) {
    float4 s0 = ((const float4*)src)[idx * 2];
    float4 s1 = ((const float4*)src)[idx * 2 + 1];
    float v[8] = {s0.x, s0.y, s0.z, s0.w, s1.x, s1.y, s1.z, s1.w};
    unsigned short o[24];
    #pragma unroll
    for (int j = 0; j < 8; j++) {
        __nv_bfloat16 hi = __float2bfloat16(v[j]);
        __nv_bfloat16 lo = __float2bfloat16(v[j] - __bfloat162float(hi));
        o[3*j] = __bfloat16_as_ushort(hi);
        o[3*j+1] = __bfloat16_as_ushort(hi);
        o[3*j+2] = __bfloat16_as_ushort(lo);
    }
    uint4* dp = (uint4*)(dst + (size_t)idx * 24);
    const uint4* op = (const uint4*)o;
    dp[0] = op[0]; dp[1] = op[1]; dp[2] = op[2];
}

// ---------------- fused prep: zero cc + done reset + cproj + weight conversions ----------------
__global__ void prep_kernel(const float* __restrict__ char_emb,
                            const float* __restrict__ Wc_ih,
                            const float* __restrict__ bc,
                            const float* __restrict__ Wc_hh,
                            const float* __restrict__ Ww_ih) {
    __shared__ float ce[NE];
    int blk = blockIdx.x, tid = threadIdx.x;
    if (blk < 8192) {
        int idx = blk * 256 + tid;
        ((float4*)g_cc)[idx] = make_float4(0.f, 0.f, 0.f, 0.f);
        if (idx < 128) g_done[idx] = 0;
    } else if (blk < 8320) {
        int c = blk - 8192;
        for (int i = tid; i < NE; i += 256) ce[i] = char_emb[c * NE + i];
        __syncthreads();
        for (int n = tid; n < 4 * NE; n += 256) {
            const float* wr = Wc_ih + (size_t)n * NE;
            float acc = bc[n];
            #pragma unroll 4
            for (int k = 0; k < NE; k++) acc += ce[k] * wr[k];
            g_cproj[c * 4 * NE + n] = acc;
        }
    } else if (blk < 8448) {
        int idx = (blk - 8320) * 256 + tid;           // n8 = 32768
        conv3_body(Wc_hh, g_wchh3, idx);
    } else {
        int idx = (blk - 8448) * 256 + tid;           // n8 = 131072
        conv3_body(Ww_ih, g_wwih3, idx);
    }
}

// ---------------- t=0 char gates: pure gather (h=0) ----------------
__global__ void gather_gates0_kernel(const int* __restrict__ char_idx) {
    int idx = blockIdx.x * blockDim.x + threadIdx.x;   // over NBS*256 float4
    int w = idx >> 8, q = idx & 255;
    int ci = char_idx[w * NC];
    ((float4*)g_gates)[(size_t)w * 256 + q] = ((const float4*)g_cproj)[(size_t)ci * 256 + q];
}

// ---------------- char LSTM cell update + triple-bf16 h emit ----------------
__global__ void char_cell_kernel() {
    int idx = blockIdx.x * blockDim.x + threadIdx.x;   // NBS*32 threads, 8 units each
    int w = idx >> 5, q = idx & 31;
    const float* gp = g_gates + (size_t)w * 1024 + q * 8;
    float4 i0 = *(const float4*)(gp);        float4 i1 = *(const float4*)(gp + 4);
    float4 f0 = *(const float4*)(gp + 256);  float4 f1 = *(const float4*)(gp + 260);
    float4 g0 = *(const float4*)(gp + 512);  float4 g1 = *(const float4*)(gp + 516);
    float4 o0 = *(const float4*)(gp + 768);  float4 o1 = *(const float4*)(gp + 772);
    float* cp = g_cc + (size_t)w * 256 + q * 8;
    float4 c0 = *(const float4*)(cp);        float4 c1 = *(const float4*)(cp + 4);
    float gi[8] = {i0.x,i0.y,i0.z,i0.w,i1.x,i1.y,i1.z,i1.w};
    float gf[8] = {f0.x,f0.y,f0.z,f0.w,f1.x,f1.y,f1.z,f1.w};
    float gg[8] = {g0.x,g0.y,g0.z,g0.w,g1.x,g1.y,g1.z,g1.w};
    float go[8] = {o0.x,o0.y,o0.z,o0.w,o1.x,o1.y,o1.z,o1.w};
    float cc[8] = {c0.x,c0.y,c0.z,c0.w,c1.x,c1.y,c1.z,c1.w};
    float h[8];
    #pragma unroll
    for (int j = 0; j < 8; j++) {
        cc[j] = sigm(gf[j]) * cc[j] + sigm(gi[j]) * tanhf(gg[j]);
        h[j] = sigm(go[j]) * tanhf(cc[j]);
    }
    *(float4*)(cp)     = make_float4(cc[0],cc[1],cc[2],cc[3]);
    *(float4*)(cp + 4) = make_float4(cc[4],cc[5],cc[6],cc[7]);
    unsigned short o[24];
    #pragma unroll
    for (int j = 0; j < 8; j++) {
        __nv_bfloat16 hi = __float2bfloat16(h[j]);
        __nv_bfloat16 lo = __float2bfloat16(h[j] - __bfloat162float(hi));
        o[3*j] = __bfloat16_as_ushort(hi);
        o[3*j+1] = __bfloat16_as_ushort(lo);
        o[3*j+2] = __bfloat16_as_ushort(hi);
    }
    uint4* dp = (uint4*)(g_h3 + (size_t)w * 768 + q * 24);
    const uint4* op = (const uint4*)o;
    dp[0] = op[0]; dp[1] = op[1]; dp[2] = op[2];
}

// ==================== mma.sync bf16 GEMM (ldmatrix + swizzle) ====================
#define KT 64

__device__ __forceinline__ void mma16816(float* d, const uint32_t* a, const uint32_t* b) {
    asm volatile(
        "mma.sync.aligned.m16n8k16.row.col.f32.bf16.bf16.f32 "
        "{%0,%1,%2,%3}, {%4,%5,%6,%7}, {%8,%9}, {%0,%1,%2,%3};"
        : "+f"(d[0]), "+f"(d[1]), "+f"(d[2]), "+f"(d[3])
        : "r"(a[0]), "r"(a[1]), "r"(a[2]), "r"(a[3]), "r"(b[0]), "r"(b[1]));
}

#define STAGE_LOAD(s, kt) do {                                                     \
    _Pragma("unroll")                                                              \
    for (int j_ = 0; j_ < 8; j_++) {                                               \
        int ch_ = tid + j_ * 256;                                                  \
        int isB_ = ch_ >> 10, c2_ = ch_ & 1023;                                    \
        int row_ = c2_ >> 3, ck_ = c2_ & 7;                                        \
        const __nv_bfloat16* gp_ = (isB_ ? B + (size_t)(n0 + row_) * K             \
                                         : A + (size_t)(m0 + row_) * K)            \
                                   + (kt) + ck_ * 8;                               \
        uint32_t sp_ = sbase + (s) * 32768 + isB_ * 16384                          \
                     + row_ * 128 + ((ck_ ^ (row_ & 7)) * 16);                     \
        asm volatile("cp.async.cg.shared.global [%0], [%1], 16;"                   \
                     :: "r"(sp_), "l"(gp_));                                       \
    }                                                                              \
    asm volatile("cp.async.commit_group;");                                        \
} while (0)

__global__ __launch_bounds__(256, 2)
void mma_gemm_kernel(const __nv_bfloat16* __restrict__ A,
                     const __nv_bfloat16* __restrict__ B,
                     float* __restrict__ C, int M, int N, int K,
                     const float* __restrict__ bias,
                     const float* __restrict__ addrows,
                     const int* __restrict__ addidx, int idx_stride) {
    extern __shared__ char smraw[];
    uint32_t sb;
    asm("{ .reg .u64 t; cvta.to.shared.u64 t, %1; cvt.u32.u64 %0, t; }"
        : "=r"(sb) : "l"(smraw));
    const uint32_t sbase = (sb + 1023u) & ~1023u;
    const int tid = threadIdx.x;
    const int lane = tid & 31, wid = tid >> 5;
    const int wm = wid >> 2, wn = wid & 3;       // 2 x 4 warp grid
    const int m0 = blockIdx.y * 128, n0 = blockIdx.x * 128;
    const int lrow = lane & 7;
    const int half8 = ((lane >> 3) & 1);
    const int khalf = (lane >> 4);

    float acc[4][4][4];
    #pragma unroll
    for (int i = 0; i < 4; i++)
        #pragma unroll
        for (int j = 0; j < 4; j++)
            #pragma unroll
            for (int q = 0; q < 4; q++) acc[i][j][q] = 0.f;

    STAGE_LOAD(0, 0);
    const int nk = K / KT;
    for (int kt = 0; kt < nk; kt++) {
        if (kt + 1 < nk) {
            STAGE_LOAD((kt + 1) & 1, (kt + 1) * KT);
            asm volatile("cp.async.wait_group 1;");
        } else {
            asm volatile("cp.async.wait_group 0;");
        }
        __syncthreads();

        const uint32_t Abase = sbase + (kt & 1) * 32768;
        const uint32_t Bbase = Abase + 16384;
        #pragma unroll
        for (int k16 = 0; k16 < KT; k16 += 16) {
            const int k8 = k16 >> 3;
            uint32_t a[4][4], b[2][4];
            #pragma unroll
            for (int mi = 0; mi < 4; mi++) {
                int row = wm * 64 + mi * 16 + lrow + half8 * 8;
                uint32_t ad = Abase + row * 128 + (((k8 + khalf) ^ lrow) * 16);
                asm volatile(
                    "ldmatrix.sync.aligned.m8n8.x4.shared.b16 {%0,%1,%2,%3}, [%4];"
                    : "=r"(a[mi][0]), "=r"(a[mi][1]), "=r"(a[mi][2]), "=r"(a[mi][3])
                    : "r"(ad));
            }
            #pragma unroll
            for (int p = 0; p < 2; p++) {
                int nrow = wn * 32 + p * 16 + khalf * 8 + lrow;
                uint32_t bd = Bbase + nrow * 128 + (((k8 + half8) ^ lrow) * 16);
                asm volatile(
                    "ldmatrix.sync.aligned.m8n8.x4.shared.b16 {%0,%1,%2,%3}, [%4];"
                    : "=r"(b[p][0]), "=r"(b[p][1]), "=r"(b[p][2]), "=r"(b[p][3])
                    : "r"(bd));
            }
            #pragma unroll
            for (int mi = 0; mi < 4; mi++)
                #pragma unroll
                for (int p = 0; p < 2; p++) {
                    mma16816(acc[mi][p * 2],     a[mi], &b[p][0]);
                    mma16816(acc[mi][p * 2 + 1], a[mi], &b[p][2]);
                }
        }
        __syncthreads();
    }

    const int r = lane >> 2, cp2 = (lane & 3) * 2;
    #pragma unroll
    for (int mi = 0; mi < 4; mi++) {
        int row0 = m0 + wm * 64 + mi * 16 + r;
        int row1 = row0 + 8;
        const float* ar0 = nullptr;
        const float* ar1 = nullptr;
        if (addrows) {
            ar0 = addrows + (size_t)addidx[(size_t)row0 * idx_stride] * N;
            ar1 = addrows + (size_t)addidx[(size_t)row1 * idx_stride] * N;
        }
        #pragma unroll
        for (int nj = 0; nj < 4; nj++) {
            int col = n0 + wn * 32 + nj * 8 + cp2;
            float v0 = acc[mi][nj][0], v1 = acc[mi][nj][1];
            float v2 = acc[mi][nj][2], v3 = acc[mi][nj][3];
            if (bias) {
                float2 b2 = *(const float2*)(bias + col);
                v0 += b2.x; v1 += b2.y; v2 += b2.x; v3 += b2.y;
            }
            if (ar0) {
                float2 a0 = *(const float2*)(ar0 + col);
                float2 a1 = *(const float2*)(ar1 + col);
                v0 += a0.x; v1 += a0.y; v2 += a1.x; v3 += a1.y;
            }
            *(float2*)(C + (size_t)row0 * N + col) = make_float2(v0, v1);
            *(float2*)(C + (size_t)row1 * N + col) = make_float2(v2, v3);
        }
    }
}
#define GEMM_SMEM (1024 + 2 * 32768)

// ---------------- gather word-LSTM input -> triple bf16 (h part copied from g_h3) ----------------
__global__ void gather_xw3_kernel(const int* __restrict__ word_idx,
                                  const float* __restrict__ word_emb) {
    int idx = blockIdx.x * blockDim.x + threadIdx.x;   // NBS*64, 8 elems each
    int w = idx >> 6, q = idx & 63;
    uint4* dp = (uint4*)(g_xw3 + (size_t)w * 1536 + q * 24);
    if (q < 32) {
        const float* src = word_emb + (size_t)word_idx[w] * NE + q * 8;
        float4 s0 = *(const float4*)(src);
        float4 s1 = *(const float4*)(src + 4);
        float v[8] = {s0.x, s0.y, s0.z, s0.w, s1.x, s1.y, s1.z, s1.w};
        unsigned short o[24];
        #pragma unroll
        for (int j = 0; j < 8; j++) {
            __nv_bfloat16 hi = __float2bfloat16(v[j]);
            __nv_bfloat16 lo = __float2bfloat16(v[j] - __bfloat162float(hi));
            o[3*j] = __bfloat16_as_ushort(hi);
            o[3*j+1] = __bfloat16_as_ushort(lo);
            o[3*j+2] = __bfloat16_as_ushort(hi);
        }
        const uint4* op = (const uint4*)o;
        dp[0] = op[0]; dp[1] = op[1]; dp[2] = op[2];
    } else {
        const uint4* sp = (const uint4*)(g_h3 + (size_t)w * 768 + (q - 32) * 24);
        dp[0] = sp[0]; dp[1] = sp[1]; dp[2] = sp[2];
    }
}

// ---------------- persistent word LSTM v3 ----------------
// 2-D partition: 4 batch-groups x 32 unit-blocks. Block = (group, ub):
//   batches group*8..+7, units ub*16..+15 (64 weight rows in smem, 130KB).
// Thread (b in 8, u in 16, half): half-dot k = half*4 + j*8.
// Atomic-free barrier: g_done[bid] = t+1; warp0 polls own group's 32 slots.
#define WSTR 520
#define HSTR 520
__global__ __launch_bounds__(256)
void word_lstm_kernel(const float* __restrict__ Whh) {
    extern __shared__ float sm[];
    float* w_s = sm;                 // [64][WSTR]
    float* h_s = sm + 64 * WSTR;     // [8][HSTR]
    const int tid = threadIdx.x;
    const int b = tid >> 5;          // 0..7   (warp = batch)
    const int u = (tid >> 1) & 15;   // 0..15
    const int half = tid & 1;
    const int group = blockIdx.x >> 5;       // 0..3
    const int ub = blockIdx.x & 31;          // 0..31
    const int ug = ub * 16 + u;              // global unit
    const int bg = group * 8 + b;            // global batch

    // load 64 weight rows: row rr = gate*16 + ulocal -> Whh[gate*NH + ub*16 + ulocal]
    for (int i = tid; i < 64 * 512; i += 256) {
        int rr = i >> 9, k = i & 511;
        int grow = (rr >> 4) * NH + ub * 16 + (rr & 15);
        w_s[rr * WSTR + k] = Whh[(size_t)grow * NH + k];
    }

    const float* wp0 = w_s + (0  + u) * WSTR;
    const float* wp1 = w_s + (16 + u) * WSTR;
    const float* wp2 = w_s + (32 + u) * WSTR;
    const float* wp3 = w_s + (48 + u) * WSTR;
    const int kofs = half * 4;
    volatile int* dp = (volatile int*)(g_done + group * 32);

    float c = 0.f;
    for (int t = 0; t < NS; ++t) {
        if (t == 0) {
            for (int i = tid; i < 8 * 128; i += 256) {
                int bb = i >> 7, kq = i & 127;
                *(float4*)(h_s + bb * HSTR + kq * 4) = make_float4(0, 0, 0, 0);
            }
        } else {
            const float* hp = g_whs + (size_t)(t - 1) * NB * NH + (size_t)(group * 8) * NH;
            for (int i = tid; i < 8 * 128; i += 256) {
                int bb = i >> 7, kq = i & 127;
                *(float4*)(h_s + bb * HSTR + kq * 4) = *(const float4*)(hp + bb * 512 + kq * 4);
            }
        }
        __syncthreads();

        // prefetch gin (independent of h)
        const float* gin = g_gin + ((size_t)bg * NS + t) * (4 * NH);
        float gi0 = gin[ug];
        float gi1 = gin[NH + ug];
        float gi2 = gin[2 * NH + ug];
        float gi3 = gin[3 * NH + ug];

        float a0 = 0.f, a1 = 0.f, a2 = 0.f, a3 = 0.f;
        const float* hr = h_s + b * HSTR;
        #pragma unroll 4
        for (int j = 0; j < 64; j++) {
            int k = kofs + j * 8;
            float4 hv = *(const float4*)(hr + k);
            float4 w0 = *(const float4*)(wp0 + k);
            float4 w1 = *(const float4*)(wp1 + k);
            float4 w2 = *(const float4*)(wp2 + k);
            float4 w3 = *(const float4*)(wp3 + k);
            a0 += hv.x * w0.x + hv.y * w0.y + hv.z * w0.z + hv.w * w0.w;
            a1 += hv.x * w1.x + hv.y * w1.y + hv.z * w1.z + hv.w * w1.w;
            a2 += hv.x * w2.x + hv.y * w2.y + hv.z * w2.z + hv.w * w2.w;
            a3 += hv.x * w3.x + hv.y * w3.y + hv.z * w3.z + hv.w * w3.w;
        }
        a0 += __shfl_xor_sync(0xffffffffu, a0, 1);
        a1 += __shfl_xor_sync(0xffffffffu, a1, 1);
        a2 += __shfl_xor_sync(0xffffffffu, a2, 1);
        a3 += __shfl_xor_sync(0xffffffffu, a3, 1);

        float iv = sigm(a0 + gi0);
        float fv = sigm(a1 + gi1);
        float gv = tanhf(a2 + gi2);
        float ov = sigm(a3 + gi3);
        c = fv * c + iv * gv;
        float h = ov * tanhf(c);
        if (half == 0)
            g_whs[(size_t)t * NB * NH + (size_t)bg * NH + ug] = h;

        __syncthreads();
        if (tid == 0) {
            __threadfence();
            *((volatile int*)&g_done[blockIdx.x]) = t + 1;
        }
        if (tid < 32) {
            int ok;
            do {
                ok = __all_sync(0xffffffffu, dp[tid] >= t + 1);
            } while (!ok);
            __threadfence();
        }
        __syncthreads();
    }
}
#define LSTM_SMEM ((64 * WSTR + 8 * HSTR) * 4)   // 149760 B

// ---------------- tag projection + log_softmax ----------------
__global__ void tag_kernel(const float* __restrict__ Wt, const float* __restrict__ bt,
                           float* __restrict__ out) {
    __shared__ float hs[8][512];
    __shared__ float lg[8][52];
    int tid = threadIdx.x, warp = tid >> 5, lane = tid & 31;
    int wbase = blockIdx.x * 8;

    for (int i = tid; i < 8 * 512; i += 256) {
        int tok = i >> 9, k = i & 511;
        int w = wbase + tok;
        int b = w >> 10, s = w & 1023;
        hs[tok][k] = g_whs[((size_t)s * NB + b) * NH + k];
    }
    __syncthreads();

    for (int tg = 0; tg < NT; ++tg) {
        const float* wr = Wt + (size_t)tg * NH;
        float p = 0.f;
        for (int k = lane; k < NH; k += 32) p += hs[warp][k] * wr[k];
        #pragma unroll
        for (int o = 16; o; o >>= 1) p += __shfl_xor_sync(0xffffffff, p, o);
        if (lane == 0) lg[warp][tg] = p + bt[tg];
    }
    __syncwarp();

    float v0 = (lane < NT) ? lg[warp][lane] : -1e30f;
    float v1 = (lane + 32 < NT) ? lg[warp][lane + 32] : -1e30f;
    float m = fmaxf(v0, v1);
    #pragma unroll
    for (int o = 16; o; o >>= 1) m = fmaxf(m, __shfl_xor_sync(0xffffffff, m, o));
    float e = ((lane < NT) ? expf(v0 - m) : 0.f) + ((lane + 32 < NT) ? expf(v1 - m) : 0.f);
    #pragma unroll
    for (int o = 16; o; o >>= 1) e += __shfl_xor_sync(0xffffffff, e, o);
    float lse = m + logf(e);

    int w = wbase + warp;
    if (lane < NT)      out[(size_t)w * NT + lane]      = v0 - lse;
    if (lane + 32 < NT) out[(size_t)w * NT + lane + 32] = v1 - lse;
}

// ---------------- host entry ----------------
extern "C" void kernel_launch(void* const* d_in, const int* in_sizes, int n_in,
                              void* d_out, int out_size) {
    const int*   char_idx = (const int*)d_in[0];
    const int*   word_idx = (const int*)d_in[1];
    const float* char_emb = (const float*)d_in[2];
    const float* word_emb = (const float*)d_in[3];
    const float* Wc_ih    = (const float*)d_in[4];
    const float* Wc_hh    = (const float*)d_in[5];
    const float* bc       = (const float*)d_in[6];
    const float* Ww_ih    = (const float*)d_in[7];
    const float* Ww_hh    = (const float*)d_in[8];
    const float* bw       = (const float*)d_in[9];
    const float* Wt       = (const float*)d_in[10];
    const float* bt       = (const float*)d_in[11];
    float* out = (float*)d_out;

    float *p_gates, *p_gin, *p_cproj;
    __nv_bfloat16 *p_h3, *p_wchh3, *p_xw3, *p_wwih3;
    cudaGetSymbolAddress((void**)&p_gates, g_gates);
    cudaGetSymbolAddress((void**)&p_gin,   g_gin);
    cudaGetSymbolAddress((void**)&p_cproj, g_cproj);
    cudaGetSymbolAddress((void**)&p_h3,    g_h3);
    cudaGetSymbolAddress((void**)&p_wchh3, g_wchh3);
    cudaGetSymbolAddress((void**)&p_xw3,   g_xw3);
    cudaGetSymbolAddress((void**)&p_wwih3, g_wwih3);

    cudaFuncSetAttribute(mma_gemm_kernel,
                         cudaFuncAttributeMaxDynamicSharedMemorySize, GEMM_SMEM);
    cudaFuncSetAttribute(word_lstm_kernel,
                         cudaFuncAttributeMaxDynamicSharedMemorySize, LSTM_SMEM);

    prep_kernel<<<8960, 256>>>(char_emb, Wc_ih, bc, Wc_hh, Ww_ih);           // 1
    gather_gates0_kernel<<<NBS, 256>>>(char_idx);                            // 2
    char_cell_kernel<<<NBS*32/256, 256>>>();                                 // 3
    for (int t = 1; t < NC; t++) {
        mma_gemm_kernel<<<dim3(1024/128, NBS/128), 256, GEMM_SMEM>>>(        // 4 = first
            p_h3, p_wchh3, p_gates, NBS, 1024, 3*NE,
            nullptr, p_cproj, char_idx + t, NC);
        char_cell_kernel<<<NBS*32/256, 256>>>();
    }

    // word input projection
    gather_xw3_kernel<<<NBS*64/256, 256>>>(word_idx, word_emb);
    mma_gemm_kernel<<<dim3(2048/128, NBS/128), 256, GEMM_SMEM>>>(
        p_xw3, p_wwih3, p_gin, NBS, 2048, 3*2*NE,
        bw, nullptr, nullptr, 0);

    // persistent word LSTM v3 (1024 steps, group-local flag barrier)
    word_lstm_kernel<<<128, 256, LSTM_SMEM>>>(Ww_hh);

    // tag projection + log_softmax
    tag_kernel<<<NBS/8, 256>>>(Wt, bt, out);
}